// round 1
// baseline (speedup 1.0000x reference)
#include <cuda_runtime.h>
#include <cuda_bf16.h>

// softplus matching jax.nn.softplus = max(x,0) + log1p(exp(-|x|))
__device__ __forceinline__ float softplus_f(float x) {
    return fmaxf(x, 0.0f) + log1pf(__expf(-fabsf(x)));
}

// One CTA per batch row. 1024 threads, CHUNK contiguous elements per thread.
// Per-thread sequential accumulation of incr[t] = (ts[t]-ts[t-1]) * f(t-1),
// then two-level block scan, then add SOC_init + exclusive offset.
template <int CHUNK>
__global__ __launch_bounds__(1024, 1)
void soc_kernel(const float4* __restrict__ X,       // (B, T, 4)
                const float*  __restrict__ SC,      // (B, 4)
                const float*  __restrict__ W1i,     // (1,4)
                const float*  __restrict__ b1i,     // (1,)
                const float*  __restrict__ W2i,     // (1,1)
                const float*  __restrict__ b2i,     // (1,)
                const float*  __restrict__ W1e,     // (1,2)
                const float*  __restrict__ b1e,     // (1,)
                const float*  __restrict__ W2e,     // (1,1)
                const float*  __restrict__ b2e,     // (1,)
                float* __restrict__ out,            // (B, T, 1)
                int T)
{
    const int b   = blockIdx.x;
    const int tid = threadIdx.x;
    const long long rowbase = (long long)b * (long long)T;

    // Per-batch scalars
    const float Q    = SC[b * 4 + 0];
    const float eta0 = SC[b * 4 + 1];
    const float R    = SC[b * 4 + 2];
    const float S3   = SC[b * 4 + 3];

    const float w1e0 = W1e[0], w1e1 = W1e[1];
    const float be1  = b1e[0];
    const float w2e  = W2e[0];
    const float be2  = b2e[0];
    const float scale = eta0 / (3600.0f * Q);

    // SOC_init from t=0 features (broadcast load, L1 hit for all threads)
    float4 x0 = X[rowbase];
    float h0 = softplus_f(x0.y * W1i[0] + x0.z * W1i[1] + x0.w * W1i[2] + R * W1i[3] + b1i[0]);
    const float SOC_init = S3 * (1.0f + (h0 * W2i[0] + b2i[0]));

    // Sequential accumulation over this thread's CHUNK elements
    const int s = tid * CHUNK;
    float4 prev;
    if (s > 0 && s < T) prev = X[rowbase + s - 1];

    float run = 0.0f;
    float vals[CHUNK];
    #pragma unroll
    for (int j = 0; j < CHUNK; j++) {
        const int t = s + j;
        float c = 0.0f;
        if (t < T) {
            float4 cur = X[rowbase + t];
            if (t > 0) {
                // f at previous timestep: I = prev.y, Temp = prev.z
                float h = softplus_f(fmaf(prev.y, w1e0, fmaf(prev.z, w1e1, be1)));
                float fprev = scale * (1.0f + fmaf(h, w2e, be2)) * prev.y;
                c = (cur.x - prev.x) * fprev;   // dt * f[t-1]
            }
            prev = cur;
        }
        run += c;
        vals[j] = run;   // inclusive within-thread prefix
    }

    // ---- Block-level exclusive scan of per-thread totals ----
    const unsigned FULL = 0xFFFFFFFFu;
    const int lane = tid & 31;
    const int warp = tid >> 5;

    float v = run;  // warp-inclusive scan
    #pragma unroll
    for (int d = 1; d < 32; d <<= 1) {
        float o = __shfl_up_sync(FULL, v, d);
        if (lane >= d) v += o;
    }

    __shared__ float warp_tot[32];
    if (lane == 31) warp_tot[warp] = v;
    __syncthreads();

    if (warp == 0) {
        float w = warp_tot[lane];
        #pragma unroll
        for (int d = 1; d < 32; d <<= 1) {
            float o = __shfl_up_sync(FULL, w, d);
            if (lane >= d) w += o;
        }
        warp_tot[lane] = w;  // inclusive warp-total prefix
    }
    __syncthreads();

    const float warp_off  = (warp > 0) ? warp_tot[warp - 1] : 0.0f;
    const float excl_off  = warp_off + (v - run);   // exclusive prefix for this thread
    const float base      = SOC_init + excl_off;

    // ---- Write out (2x STG.128 when full chunk in-bounds) ----
    if (s + CHUNK <= T) {
        float4* o4 = reinterpret_cast<float4*>(out + rowbase + s);
        #pragma unroll
        for (int k = 0; k < CHUNK / 4; k++) {
            float4 ov;
            ov.x = base + vals[k * 4 + 0];
            ov.y = base + vals[k * 4 + 1];
            ov.z = base + vals[k * 4 + 2];
            ov.w = base + vals[k * 4 + 3];
            o4[k] = ov;
        }
    } else {
        for (int j = 0; j < CHUNK; j++) {
            int t = s + j;
            if (t < T) out[rowbase + t] = base + vals[j];
        }
    }
}

extern "C" void kernel_launch(void* const* d_in, const int* in_sizes, int n_in,
                              void* d_out, int out_size)
{
    const float4* X  = (const float4*)d_in[0];   // (B, T, 4) fp32
    const float* SC  = (const float*)d_in[1];    // (B, 4)
    const float* W1i = (const float*)d_in[2];
    const float* b1i = (const float*)d_in[3];
    const float* W2i = (const float*)d_in[4];
    const float* b2i = (const float*)d_in[5];
    const float* W1e = (const float*)d_in[6];
    const float* b1e = (const float*)d_in[7];
    const float* W2e = (const float*)d_in[8];
    const float* b2e = (const float*)d_in[9];
    float* out = (float*)d_out;

    const int B = in_sizes[1] / 4;               // SC is (B,4)
    const int T = in_sizes[0] / (B * 4);         // X is (B,T,4)

    // 1024 threads x 8 elems = 8192 per CTA (exact for T=8192; guarded otherwise)
    soc_kernel<8><<<B, 1024>>>(X, SC, W1i, b1i, W2i, b2i, W1e, b1e, W2e, b2e, out, T);
}

// round 2
// speedup vs baseline: 1.2887x; 1.2887x over previous
#include <cuda_runtime.h>
#include <cuda_bf16.h>

// fast softplus: max(x,0) + log(1 + exp(-|x|)); abs error ~1e-7, tolerance is 1e-3
__device__ __forceinline__ float softplus_f(float x) {
    return fmaxf(x, 0.0f) + __logf(1.0f + __expf(-fabsf(x)));
}

// One CTA per batch row, 1024 threads, T<=8192.
// Phase 1: warp-coalesced loads of X (element e = j*1024+tid), compute per-step
//          increment incr[e] = dt * f[e-1], stage in SMEM (4B/elem).
// Phase 2: contiguous-per-thread scan from SMEM + two-level block scan, write out.
template <int CHUNK, int NTHREADS>
__global__ __launch_bounds__(NTHREADS, 1)
void soc_kernel(const float4* __restrict__ X,       // (B, T, 4)
                const float*  __restrict__ SC,      // (B, 4)
                const float*  __restrict__ W1i, const float* __restrict__ b1i,
                const float*  __restrict__ W2i, const float* __restrict__ b2i,
                const float*  __restrict__ W1e, const float* __restrict__ b1e,
                const float*  __restrict__ W2e, const float* __restrict__ b2e,
                float* __restrict__ out,            // (B, T)
                int T)
{
    __shared__ float incr[CHUNK * NTHREADS];   // 32 KB
    __shared__ float warp_tot[NTHREADS / 32];

    const int b   = blockIdx.x;
    const int tid = threadIdx.x;
    const long long rowbase = (long long)b * (long long)T;

    // Per-batch scalars
    const float Q    = SC[b * 4 + 0];
    const float eta0 = SC[b * 4 + 1];
    const float R    = SC[b * 4 + 2];
    const float S3   = SC[b * 4 + 3];

    const float w1e0 = W1e[0], w1e1 = W1e[1];
    const float be1  = b1e[0];
    const float w2e  = W2e[0];
    const float be2  = b2e[0];
    const float scale = eta0 / (3600.0f * Q);

    // SOC_init from t=0 features (broadcast load)
    float4 x0 = X[rowbase];
    float h0 = softplus_f(x0.y * W1i[0] + x0.z * W1i[1] + x0.w * W1i[2] + R * W1i[3] + b1i[0]);
    const float SOC_init = S3 * (1.0f + (h0 * W2i[0] + b2i[0]));

    // ---- Phase 1: coalesced loads, compute incr[e], stage to SMEM ----
    #pragma unroll
    for (int j = 0; j < CHUNK; j++) {
        const int e = j * NTHREADS + tid;
        float c = 0.0f;
        if (e > 0 && e < T) {
            float4 cur = X[rowbase + e];       // warp: 512B contiguous
            float4 pv  = X[rowbase + e - 1];   // warp: 512B contiguous (L1 overlap)
            float h = softplus_f(fmaf(pv.y, w1e0, fmaf(pv.z, w1e1, be1)));
            float fprev = scale * (1.0f + fmaf(h, w2e, be2)) * pv.y;
            c = (cur.x - pv.x) * fprev;        // dt * f[t-1]
        }
        incr[j * NTHREADS + tid] = c;          // coalesced STS
    }
    __syncthreads();

    // ---- Phase 2: per-thread sequential prefix over contiguous chunk ----
    const int s = tid * CHUNK;
    float vals[CHUNK];
    float run = 0.0f;
    {
        const float4* inc4 = reinterpret_cast<const float4*>(incr);
        #pragma unroll
        for (int k = 0; k < CHUNK / 4; k++) {
            float4 iv = inc4[tid * (CHUNK / 4) + k];     // LDS.128
            run += iv.x; vals[k * 4 + 0] = run;
            run += iv.y; vals[k * 4 + 1] = run;
            run += iv.z; vals[k * 4 + 2] = run;
            run += iv.w; vals[k * 4 + 3] = run;
        }
    }

    // ---- Block-level exclusive scan of per-thread totals ----
    const unsigned FULL = 0xFFFFFFFFu;
    const int lane = tid & 31;
    const int warp = tid >> 5;

    float v = run;  // warp-inclusive scan
    #pragma unroll
    for (int d = 1; d < 32; d <<= 1) {
        float o = __shfl_up_sync(FULL, v, d);
        if (lane >= d) v += o;
    }
    if (lane == 31) warp_tot[warp] = v;
    __syncthreads();

    if (warp == 0) {
        float w = warp_tot[lane];
        #pragma unroll
        for (int d = 1; d < 32; d <<= 1) {
            float o = __shfl_up_sync(FULL, w, d);
            if (lane >= d) w += o;
        }
        warp_tot[lane] = w;
    }
    __syncthreads();

    const float warp_off = (warp > 0) ? warp_tot[warp - 1] : 0.0f;
    const float base     = SOC_init + warp_off + (v - run);  // exclusive prefix

    // ---- Write out ----
    if (s + CHUNK <= T) {
        float4* o4 = reinterpret_cast<float4*>(out + rowbase + s);
        #pragma unroll
        for (int k = 0; k < CHUNK / 4; k++) {
            float4 ov;
            ov.x = base + vals[k * 4 + 0];
            ov.y = base + vals[k * 4 + 1];
            ov.z = base + vals[k * 4 + 2];
            ov.w = base + vals[k * 4 + 3];
            o4[k] = ov;
        }
    } else {
        for (int j = 0; j < CHUNK; j++) {
            int t = s + j;
            if (t < T) out[rowbase + t] = base + vals[j];
        }
    }
}

extern "C" void kernel_launch(void* const* d_in, const int* in_sizes, int n_in,
                              void* d_out, int out_size)
{
    const float4* X  = (const float4*)d_in[0];   // (B, T, 4) fp32
    const float* SC  = (const float*)d_in[1];    // (B, 4)
    const float* W1i = (const float*)d_in[2];
    const float* b1i = (const float*)d_in[3];
    const float* W2i = (const float*)d_in[4];
    const float* b2i = (const float*)d_in[5];
    const float* W1e = (const float*)d_in[6];
    const float* b1e = (const float*)d_in[7];
    const float* W2e = (const float*)d_in[8];
    const float* b2e = (const float*)d_in[9];
    float* out = (float*)d_out;

    const int B = in_sizes[1] / 4;               // SC is (B,4)
    const int T = in_sizes[0] / (B * 4);         // X is (B,T,4)

    soc_kernel<8, 1024><<<B, 1024>>>(X, SC, W1i, b1i, W2i, b2i, W1e, b1e, W2e, b2e, out, T);
}